// round 4
// baseline (speedup 1.0000x reference)
#include <cuda_runtime.h>
#include <cuda_fp16.h>
#include <math.h>

#define NNODES 80000
#define DIM    128
#define DEMB   64
#define NT     128
#define NG     8000
#define NUMP   40000
#define NEMAX  2560000

typedef unsigned long long ull;

__device__ __forceinline__ ull ffma2(ull a, ull b, ull c) {
    ull d;
    asm("fma.rn.f32x2 %0, %1, %2, %3;" : "=l"(d) : "l"(a), "l"(b), "l"(c));
    return d;
}
__device__ __forceinline__ ull bcast2(float a) {
    ull d;
    asm("mov.b64 %0, {%1, %1};" : "=l"(d) : "f"(a));
    return d;
}
__device__ __forceinline__ float2 unpack2(ull v) {
    float2 f;
    asm("mov.b64 {%0, %1}, %2;" : "=f"(f.x), "=f"(f.y) : "l"(v));
    return f;
}

// ---------------- scratch (static device arrays; no allocation) ----------------
__device__ int g_rowptr[NNODES + 1];
__device__ int g_cursor[NNODES];
__device__ int g_flag[NNODES];
__device__ int g_bsum[128];
__device__ int g_esrc[NEMAX];                                 // CSR: src per edge, grouped by dst
__device__ __align__(16) __half g_xh[(size_t)NNODES * DIM];   // fp16 copy of x (gather traffic /2)
__device__ __align__(16) float g_xa[(size_t)NNODES * DIM];    // agg1 output (pre-scaled by 1/deg)
__device__ __align__(16) float g_p [(size_t)NNODES * DEMB];   // relu(xa@W1+b1)@W2
__device__ __align__(16) float g_pa[(size_t)NNODES * DEMB];   // agg2 output (flagged rows only)
__device__ __align__(16) float g_At[DIM * NT];                // A transposed [k][t]
__device__ __align__(16) float g_Bt[(size_t)DIM * NG];        // B transposed [k][g]

// ---------------- x -> fp16 ----------------
__global__ void tohalf_kernel(const float* __restrict__ x) {
    int i = blockIdx.x * blockDim.x + threadIdx.x;   // one per 8 floats
    if (i >= NNODES * DIM / 8) return;
    float4 a = reinterpret_cast<const float4*>(x)[2 * i];
    float4 b = reinterpret_cast<const float4*>(x)[2 * i + 1];
    __half2 h0 = __floats2half2_rn(a.x, a.y);
    __half2 h1 = __floats2half2_rn(a.z, a.w);
    __half2 h2 = __floats2half2_rn(b.x, b.y);
    __half2 h3 = __floats2half2_rn(b.z, b.w);
    uint4 o;
    o.x = *reinterpret_cast<unsigned*>(&h0);
    o.y = *reinterpret_cast<unsigned*>(&h1);
    o.z = *reinterpret_cast<unsigned*>(&h2);
    o.w = *reinterpret_cast<unsigned*>(&h3);
    reinterpret_cast<uint4*>(g_xh)[i] = o;
}

// ---------------- zero counters/flags ----------------
__global__ void zero_kernel() {
    int i = blockIdx.x * blockDim.x + threadIdx.x;
    if (i <= NNODES) g_rowptr[i] = 0;
    if (i <  NNODES) g_flag[i] = 0;
}

__global__ void flag_kernel(const int* __restrict__ tf, const int* __restrict__ gene) {
    int i = blockIdx.x * blockDim.x + threadIdx.x;
    if (i < NT) g_flag[NUMP + tf[i]]   = 1;
    if (i < NG) g_flag[NUMP + gene[i]] = 1;
}

// ---------------- CSR build: histogram -> scan -> scatter ----------------
__global__ void hist_kernel(const int* __restrict__ dst, int ne) {
    int e = blockIdx.x * blockDim.x + threadIdx.x;
    if (e < ne) atomicAdd(&g_rowptr[dst[e] + 1], 1);
}

__global__ __launch_bounds__(1024) void scan1_kernel() {
    __shared__ int wsum[32];
    int gid = blockIdx.x * 1024 + threadIdx.x;
    int lane = threadIdx.x & 31, wid = threadIdx.x >> 5;
    int s = (gid <= NNODES) ? g_rowptr[gid] : 0;
#pragma unroll
    for (int o = 1; o < 32; o <<= 1) { int t = __shfl_up_sync(0xffffffffu, s, o); if (lane >= o) s += t; }
    if (lane == 31) wsum[wid] = s;
    __syncthreads();
    if (wid == 0) {
        int w = wsum[lane];
#pragma unroll
        for (int o = 1; o < 32; o <<= 1) { int t = __shfl_up_sync(0xffffffffu, w, o); if (lane >= o) w += t; }
        wsum[lane] = w;
    }
    __syncthreads();
    if (wid > 0) s += wsum[wid - 1];
    if (gid <= NNODES) g_rowptr[gid] = s;
    if (threadIdx.x == 1023) g_bsum[blockIdx.x] = s;
}

__global__ void scan2_kernel(int nb) {
    int lane = threadIdx.x;
    int carry = 0;
    for (int base = 0; base < nb; base += 32) {
        int v = (base + lane < nb) ? g_bsum[base + lane] : 0;
#pragma unroll
        for (int o = 1; o < 32; o <<= 1) { int t = __shfl_up_sync(0xffffffffu, v, o); if (lane >= o) v += t; }
        v += carry;
        if (base + lane < nb) g_bsum[base + lane] = v;
        carry = __shfl_sync(0xffffffffu, v, 31);
    }
}

// add block offsets AND seed g_cursor = rowptr (start offsets)
__global__ __launch_bounds__(1024) void scan3_kernel() {
    int gid = blockIdx.x * 1024 + threadIdx.x;
    if (gid > NNODES) return;
    int v = g_rowptr[gid];
    if (blockIdx.x > 0) v += g_bsum[blockIdx.x - 1];
    g_rowptr[gid] = v;
    if (gid < NNODES) g_cursor[gid] = v;
}

__global__ void scatter_kernel(const int* __restrict__ src, const int* __restrict__ dst, int ne) {
    int e = blockIdx.x * blockDim.x + threadIdx.x;
    if (e >= ne) return;
    int pos = atomicAdd(&g_cursor[dst[e]], 1);
    g_esrc[pos] = src[e];
}

// ---------------- agg1 via CSR (fp16 gather, fp32 accum): xa[d] = mean x[s] ----------------
__global__ __launch_bounds__(256) void agg1_csr_kernel() {
    int d = blockIdx.x * 8 + (threadIdx.x >> 5);
    if (d >= NNODES) return;
    int lane = threadIdx.x & 31;
    int beg = g_rowptr[d], end = g_rowptr[d + 1];
    float4 acc = make_float4(0.f, 0.f, 0.f, 0.f);
    int j = beg;
    for (; j + 1 < end; j += 2) {
        int s0 = g_esrc[j], s1 = g_esrc[j + 1];
        uint2 v0 = reinterpret_cast<const uint2*>(g_xh + (size_t)s0 * DIM)[lane];
        uint2 v1 = reinterpret_cast<const uint2*>(g_xh + (size_t)s1 * DIM)[lane];
        float2 a0 = __half22float2(*reinterpret_cast<__half2*>(&v0.x));
        float2 a1 = __half22float2(*reinterpret_cast<__half2*>(&v0.y));
        float2 b0 = __half22float2(*reinterpret_cast<__half2*>(&v1.x));
        float2 b1 = __half22float2(*reinterpret_cast<__half2*>(&v1.y));
        acc.x += a0.x + b0.x; acc.y += a0.y + b0.y;
        acc.z += a1.x + b1.x; acc.w += a1.y + b1.y;
    }
    if (j < end) {
        int s0 = g_esrc[j];
        uint2 v0 = reinterpret_cast<const uint2*>(g_xh + (size_t)s0 * DIM)[lane];
        float2 a0 = __half22float2(*reinterpret_cast<__half2*>(&v0.x));
        float2 a1 = __half22float2(*reinterpret_cast<__half2*>(&v0.y));
        acc.x += a0.x; acc.y += a0.y; acc.z += a1.x; acc.w += a1.y;
    }
    float inv = 1.f / fmaxf((float)(end - beg), 1.f);
    acc.x *= inv; acc.y *= inv; acc.z *= inv; acc.w *= inv;
    reinterpret_cast<float4*>(g_xa + (size_t)d * DIM)[lane] = acc;
}

// ---------------- agg2 via CSR (flagged dsts only): pa[d] = mean p[s] ----------------
__global__ __launch_bounds__(256) void agg2_csr_kernel() {
    int d = blockIdx.x * 8 + (threadIdx.x >> 5);
    if (d >= NNODES) return;
    if (!g_flag[d]) return;
    int lane = threadIdx.x & 31;
    int beg = g_rowptr[d], end = g_rowptr[d + 1];
    float2 acc = make_float2(0.f, 0.f);
    int j = beg;
    for (; j + 1 < end; j += 2) {
        int s0 = g_esrc[j], s1 = g_esrc[j + 1];
        float2 v0 = reinterpret_cast<const float2*>(g_p + (size_t)s0 * DEMB)[lane];
        float2 v1 = reinterpret_cast<const float2*>(g_p + (size_t)s1 * DEMB)[lane];
        acc.x += v0.x + v1.x; acc.y += v0.y + v1.y;
    }
    if (j < end) {
        int s0 = g_esrc[j];
        float2 v0 = reinterpret_cast<const float2*>(g_p + (size_t)s0 * DEMB)[lane];
        acc.x += v0.x; acc.y += v0.y;
    }
    float inv = 1.f / fmaxf((float)(end - beg), 1.f);
    reinterpret_cast<float2*>(g_pa + (size_t)d * DEMB)[lane] = make_float2(acc.x * inv, acc.y * inv);
}

// ---------------- fused GEMM: p = relu(xa@W1 + b1) @ W2   (64 rows/block, 512 threads, FFMA2) ------
__global__ __launch_bounds__(512) void fused_gemm_kernel(
    const float* __restrict__ W1, const float* __restrict__ b1,
    const float* __restrict__ W2) {
    extern __shared__ float sm[];
    float* W1s = sm;                       // 128*128
    float* W2s = W1s + 128 * 128;          // 128*64
    float* Is  = W2s + 128 * 64;           // 64*128
    float* Hs  = Is  + 64 * 128;           // 64*128
    float* b1s = Hs  + 64 * 128;           // 128
    int tid = threadIdx.x;

    for (int i = tid; i < 128 * 128 / 4; i += 512)
        reinterpret_cast<float4*>(W1s)[i] = reinterpret_cast<const float4*>(W1)[i];
    for (int i = tid; i < 128 * 64 / 4; i += 512)
        reinterpret_cast<float4*>(W2s)[i] = reinterpret_cast<const float4*>(W2)[i];
    if (tid < 128) b1s[tid] = b1[tid];

    int row0 = blockIdx.x * 64;  // 1250 blocks * 64 = 80000 exact
    for (int i = tid; i < 64 * DIM / 4; i += 512)
        reinterpret_cast<float4*>(Is)[i] =
            reinterpret_cast<const float4*>(g_xa + (size_t)row0 * DIM)[i];
    __syncthreads();

    int tr = tid >> 5, tc = tid & 31;   // tr 0..15, tc 0..31

    // phase 1: H = relu(Is @ W1 + b1); thread -> 4 rows x 4 cols (2 f32x2 pairs)
    {
        ull acc[4][2];
#pragma unroll
        for (int i = 0; i < 4; i++) { acc[i][0] = 0ull; acc[i][1] = 0ull; }

        for (int d0 = 0; d0 < DIM; d0 += 4) {
            float ar[4][4];
#pragma unroll
            for (int i = 0; i < 4; i++) {
                float4 t = reinterpret_cast<const float4*>(Is + (tr * 4 + i) * DIM)[d0 >> 2];
                ar[i][0] = t.x; ar[i][1] = t.y; ar[i][2] = t.z; ar[i][3] = t.w;
            }
#pragma unroll
            for (int dd = 0; dd < 4; dd++) {
                ulonglong2 wv = *reinterpret_cast<const ulonglong2*>(W1s + (d0 + dd) * 128 + tc * 4);
#pragma unroll
                for (int i = 0; i < 4; i++) {
                    ull ap = bcast2(ar[i][dd]);
                    acc[i][0] = ffma2(ap, wv.x, acc[i][0]);
                    acc[i][1] = ffma2(ap, wv.y, acc[i][1]);
                }
            }
        }
        float4 bv = reinterpret_cast<const float4*>(b1s)[tc];
#pragma unroll
        for (int i = 0; i < 4; i++) {
            float2 lo = unpack2(acc[i][0]);
            float2 hi = unpack2(acc[i][1]);
            float4 o;
            o.x = fmaxf(lo.x + bv.x, 0.f);
            o.y = fmaxf(lo.y + bv.y, 0.f);
            o.z = fmaxf(hi.x + bv.z, 0.f);
            o.w = fmaxf(hi.y + bv.w, 0.f);
            reinterpret_cast<float4*>(Hs + (tr * 4 + i) * DIM)[tc] = o;
        }
    }
    __syncthreads();

    // phase 2: P = Hs @ W2; thread -> 4 rows x 2 cols (1 f32x2 pair)
    {
        ull acc[4];
#pragma unroll
        for (int i = 0; i < 4; i++) acc[i] = 0ull;

        for (int d0 = 0; d0 < DIM; d0 += 4) {
            float ar[4][4];
#pragma unroll
            for (int i = 0; i < 4; i++) {
                float4 t = reinterpret_cast<const float4*>(Hs + (tr * 4 + i) * DIM)[d0 >> 2];
                ar[i][0] = t.x; ar[i][1] = t.y; ar[i][2] = t.z; ar[i][3] = t.w;
            }
#pragma unroll
            for (int dd = 0; dd < 4; dd++) {
                ull wp = *reinterpret_cast<const ull*>(W2s + (d0 + dd) * 64 + tc * 2);
#pragma unroll
                for (int i = 0; i < 4; i++)
                    acc[i] = ffma2(bcast2(ar[i][dd]), wp, acc[i]);
            }
        }
#pragma unroll
        for (int i = 0; i < 4; i++) {
            int row = row0 + tr * 4 + i;
            float2 o = unpack2(acc[i]);
            reinterpret_cast<float2*>(g_p + (size_t)row * DEMB)[tc] = o;
        }
    }
}

// ---------------- half-MLP: OutT[k][r] = sum_d (pa[node_r][d] + b2[d]) * Whalf[d][k] (+bm1[k]) ------
__global__ __launch_bounds__(128) void half_mlp_kernel(
    const int* __restrict__ list, int nrows,
    const float* __restrict__ Whalf, const float* __restrict__ b2,
    const float* __restrict__ bm1, float* __restrict__ OutT, int ldo) {
    __shared__ __align__(8) float Wst[128 * 66];   // transposed [t][d], pad 66 (even) for ull loads
    __shared__ __align__(8) float es[DEMB];
    int tid = threadIdx.x;  // 128 (= t)

#pragma unroll 4
    for (int d = 0; d < DEMB; d++) Wst[tid * 66 + d] = Whalf[d * DIM + tid];
    float base = bm1 ? bm1[tid] : 0.f;

    for (int r = blockIdx.x; r < nrows; r += gridDim.x) {
        __syncthreads();
        if (tid < DEMB) {
            int node = NUMP + list[r];
            es[tid] = g_pa[(size_t)node * DEMB + tid] + b2[tid];
        }
        __syncthreads();
        ull acc = 0ull;
#pragma unroll 8
        for (int d = 0; d < DEMB; d += 2) {
            ull ep = *reinterpret_cast<const ull*>(es + d);
            ull wp = *reinterpret_cast<const ull*>(Wst + tid * 66 + d);
            acc = ffma2(ep, wp, acc);
        }
        float2 a2 = unpack2(acc);
        OutT[(size_t)tid * ldo + r] = base + a2.x + a2.y;
    }
}

// ---------------- pair kernel: out[t*NG+g] = softmax( relu(A[t]+B[g]) @ Wm2 + bm2 ) ----------------
__global__ __launch_bounds__(256) void pair_kernel(
    const float* __restrict__ Wm2, const float* __restrict__ bm2, float* __restrict__ out) {
    extern __shared__ float sm[];
    float* As = sm;                       // [k][t] 128*128
    float* Bs = sm + DIM * NT;            // [k][gl] 128*32
    float2* w2 = reinterpret_cast<float2*>(sm + DIM * NT + DIM * 32);
    int tid = threadIdx.x;  // 256

    for (int i = tid; i < DIM * NT / 4; i += 256)
        reinterpret_cast<float4*>(As)[i] = reinterpret_cast<const float4*>(g_At)[i];
    int g0 = blockIdx.x * 32;
    for (int i = tid; i < DIM * 32; i += 256) {
        int k = i >> 5, gl = i & 31;
        Bs[i] = g_Bt[(size_t)k * NG + g0 + gl];
    }
    if (tid < DIM) w2[tid] = reinterpret_cast<const float2*>(Wm2)[tid];
    __syncthreads();

    float bo0 = bm2[0], bo1 = bm2[1];
    int lane = tid & 31, warp = tid >> 5;
    ull accp[16];
#pragma unroll
    for (int i = 0; i < 16; i++) accp[i] = 0ull;

#pragma unroll 4
    for (int k = 0; k < DIM; k++) {
        float bv = Bs[k * 32 + lane];
        ull wp = *reinterpret_cast<const ull*>(&w2[k]);
#pragma unroll
        for (int i = 0; i < 16; i++) {
            float a = As[k * DIM + warp + 8 * i];
            float v = fmaxf(a + bv, 0.f);
            accp[i] = ffma2(bcast2(v), wp, accp[i]);
        }
    }

#pragma unroll
    for (int i = 0; i < 16; i++) {
        int t = warp + 8 * i;
        float2 a2 = unpack2(accp[i]);
        float o0 = a2.x + bo0, o1 = a2.y + bo1;
        float m  = fmaxf(o0, o1);
        float e0 = __expf(o0 - m), e1 = __expf(o1 - m);
        float inv = 1.f / (e0 + e1);
        reinterpret_cast<float2*>(out)[(size_t)t * NG + g0 + lane] = make_float2(e0 * inv, e1 * inv);
    }
}

// ---------------- launch ----------------
extern "C" void kernel_launch(void* const* d_in, const int* in_sizes, int n_in,
                              void* d_out, int out_size) {
    const float* x   = (const float*)d_in[0];
    const float* W1  = (const float*)d_in[1];
    const float* b1  = (const float*)d_in[2];
    const float* W2  = (const float*)d_in[3];
    const float* b2  = (const float*)d_in[4];
    const float* Wm1 = (const float*)d_in[5];
    const float* bm1 = (const float*)d_in[6];
    const float* Wm2 = (const float*)d_in[7];
    const float* bm2 = (const float*)d_in[8];
    const int* edges = (const int*)d_in[9];
    const int* tf    = (const int*)d_in[11];
    const int* gene  = (const int*)d_in[12];
    int ne = in_sizes[9] / 2;
    const int* src = edges;
    const int* dst = edges + ne;
    float* out = (float*)d_out;

    const int fused_smem = (128 * 128 + 128 * 64 + 64 * 128 + 64 * 128 + 128) * 4;
    cudaFuncSetAttribute(fused_gemm_kernel, cudaFuncAttributeMaxDynamicSharedMemorySize, fused_smem);
    cudaFuncSetAttribute(pair_kernel, cudaFuncAttributeMaxDynamicSharedMemorySize,
                         (DIM * NT + DIM * 32) * 4 + DIM * 8);

    void *p_At, *p_Bt;
    cudaGetSymbolAddress(&p_At, g_At);
    cudaGetSymbolAddress(&p_Bt, g_Bt);

    const int nb_scan = (NNODES + 1 + 1023) / 1024;  // 79

    tohalf_kernel<<<(NNODES * DIM / 8 + 255) / 256, 256>>>(x);
    zero_kernel<<<(NNODES + 1 + 255) / 256, 256>>>();
    flag_kernel<<<(NG + 255) / 256, 256>>>(tf, gene);
    hist_kernel<<<(ne + 255) / 256, 256>>>(dst, ne);
    scan1_kernel<<<nb_scan, 1024>>>();
    scan2_kernel<<<1, 32>>>(nb_scan);
    scan3_kernel<<<nb_scan, 1024>>>();
    scatter_kernel<<<(ne + 255) / 256, 256>>>(src, dst, ne);
    agg1_csr_kernel<<<NNODES / 8, 256>>>();
    fused_gemm_kernel<<<NNODES / 64, 512, fused_smem>>>(W1, b1, W2);
    agg2_csr_kernel<<<NNODES / 8, 256>>>();
    half_mlp_kernel<<<NT, 128>>>(tf, NT, Wm1, b2, nullptr, (float*)p_At, NT);
    half_mlp_kernel<<<1000, 128>>>(gene, NG, Wm1 + 64 * DIM, b2, bm1, (float*)p_Bt, NG);
    pair_kernel<<<NG / 32, 256, (DIM * NT + DIM * 32) * 4 + DIM * 8>>>(Wm2, bm2, out);
}

// round 5
// speedup vs baseline: 1.1188x; 1.1188x over previous
#include <cuda_runtime.h>
#include <cuda_fp16.h>
#include <math.h>

#define NNODES 80000
#define DIM    128
#define DEMB   64
#define NT     128
#define NG     8000
#define NUMP   40000
#define NEMAX  2560000

typedef unsigned long long ull;

__device__ __forceinline__ ull ffma2(ull a, ull b, ull c) {
    ull d;
    asm("fma.rn.f32x2 %0, %1, %2, %3;" : "=l"(d) : "l"(a), "l"(b), "l"(c));
    return d;
}
__device__ __forceinline__ ull bcast2(float a) {
    ull d;
    asm("mov.b64 %0, {%1, %1};" : "=l"(d) : "f"(a));
    return d;
}
__device__ __forceinline__ float2 unpack2(ull v) {
    float2 f;
    asm("mov.b64 {%0, %1}, %2;" : "=f"(f.x), "=f"(f.y) : "l"(v));
    return f;
}

// ---------------- scratch (static device arrays; no allocation) ----------------
__device__ int g_rowptr[NNODES + 1];
__device__ int g_cursor[NNODES];
__device__ int g_flag[NNODES];
__device__ int g_list[NT + NG];
__device__ int g_nlist;
__device__ int g_bsum[128];
__device__ int g_esrc[NEMAX];                                 // CSR: src per edge, grouped by dst
__device__ __align__(16) __half g_xh[(size_t)NNODES * DIM];   // fp16 copy of x
__device__ __align__(16) float g_xa[(size_t)NNODES * DIM];    // agg1 output (pre-scaled by 1/deg)
__device__ __align__(16) float g_p [(size_t)NNODES * DEMB];   // relu(xa@W1+b1)@W2
__device__ __align__(16) float g_pa[(size_t)NNODES * DEMB];   // agg2 output (listed rows only)
__device__ __align__(16) float g_At[DIM * NT];                // A transposed [k][t]
__device__ __align__(16) float g_Bt[(size_t)DIM * NG];        // B transposed [k][g]

// ---------------- zero counters/flags ----------------
__global__ void zero_kernel() {
    int i = blockIdx.x * blockDim.x + threadIdx.x;
    if (i <= NNODES) g_rowptr[i] = 0;
    if (i <  NNODES) g_flag[i] = 0;
    if (i == 0) g_nlist = 0;
}

// ---------------- combo: hist + x->fp16 + flag/list (all depend only on zero) ----------------
__global__ void combo_kernel(const float* __restrict__ x,
                             const int* __restrict__ dst, int ne, int hb,
                             const int* __restrict__ tf, const int* __restrict__ gene) {
    int b = blockIdx.x;
    if (b < hb) {                       // histogram
        int e = b * 256 + threadIdx.x;
        if (e < ne) atomicAdd(&g_rowptr[dst[e] + 1], 1);
    } else if (b < hb + 5000) {         // x -> fp16 (one thread per 8 floats)
        int i = (b - hb) * 256 + threadIdx.x;
        if (i < NNODES * DIM / 8) {
            float4 a = reinterpret_cast<const float4*>(x)[2 * i];
            float4 bq = reinterpret_cast<const float4*>(x)[2 * i + 1];
            __half2 h0 = __floats2half2_rn(a.x, a.y);
            __half2 h1 = __floats2half2_rn(a.z, a.w);
            __half2 h2 = __floats2half2_rn(bq.x, bq.y);
            __half2 h3 = __floats2half2_rn(bq.z, bq.w);
            uint4 o;
            o.x = *reinterpret_cast<unsigned*>(&h0);
            o.y = *reinterpret_cast<unsigned*>(&h1);
            o.z = *reinterpret_cast<unsigned*>(&h2);
            o.w = *reinterpret_cast<unsigned*>(&h3);
            reinterpret_cast<uint4*>(g_xh)[i] = o;
        }
    } else {                            // flag + compact list
        int i = (b - hb - 5000) * 256 + threadIdx.x;
        if (i < NT) {
            int nd = NUMP + tf[i];
            if (atomicExch(&g_flag[nd], 1) == 0) g_list[atomicAdd(&g_nlist, 1)] = nd;
        }
        if (i < NG) {
            int nd = NUMP + gene[i];
            if (atomicExch(&g_flag[nd], 1) == 0) g_list[atomicAdd(&g_nlist, 1)] = nd;
        }
    }
}

// ---------------- scan over g_rowptr ----------------
__global__ __launch_bounds__(1024) void scan1_kernel() {
    __shared__ int wsum[32];
    int gid = blockIdx.x * 1024 + threadIdx.x;
    int lane = threadIdx.x & 31, wid = threadIdx.x >> 5;
    int s = (gid <= NNODES) ? g_rowptr[gid] : 0;
#pragma unroll
    for (int o = 1; o < 32; o <<= 1) { int t = __shfl_up_sync(0xffffffffu, s, o); if (lane >= o) s += t; }
    if (lane == 31) wsum[wid] = s;
    __syncthreads();
    if (wid == 0) {
        int w = wsum[lane];
#pragma unroll
        for (int o = 1; o < 32; o <<= 1) { int t = __shfl_up_sync(0xffffffffu, w, o); if (lane >= o) w += t; }
        wsum[lane] = w;
    }
    __syncthreads();
    if (wid > 0) s += wsum[wid - 1];
    if (gid <= NNODES) g_rowptr[gid] = s;
    if (threadIdx.x == 1023) g_bsum[blockIdx.x] = s;
}

__global__ void scan2_kernel(int nb) {
    int lane = threadIdx.x;
    int carry = 0;
    for (int base = 0; base < nb; base += 32) {
        int v = (base + lane < nb) ? g_bsum[base + lane] : 0;
#pragma unroll
        for (int o = 1; o < 32; o <<= 1) { int t = __shfl_up_sync(0xffffffffu, v, o); if (lane >= o) v += t; }
        v += carry;
        if (base + lane < nb) g_bsum[base + lane] = v;
        carry = __shfl_sync(0xffffffffu, v, 31);
    }
}

__global__ __launch_bounds__(1024) void scan3_kernel() {
    int gid = blockIdx.x * 1024 + threadIdx.x;
    if (gid > NNODES) return;
    int v = g_rowptr[gid];
    if (blockIdx.x > 0) v += g_bsum[blockIdx.x - 1];
    g_rowptr[gid] = v;
    if (gid < NNODES) g_cursor[gid] = v;
}

__global__ void scatter_kernel(const int* __restrict__ src, const int* __restrict__ dst, int ne) {
    int e = blockIdx.x * blockDim.x + threadIdx.x;
    if (e >= ne) return;
    int pos = atomicAdd(&g_cursor[dst[e]], 1);
    g_esrc[pos] = src[e];
}

// ---------------- agg1: warp per dst, half-warps gather 2 edges at once (fp16 rows) ----------------
__global__ __launch_bounds__(256) void agg1_csr_kernel() {
    int d = blockIdx.x * 8 + (threadIdx.x >> 5);
    if (d >= NNODES) return;
    int lane = threadIdx.x & 31;
    int half = lane >> 4;       // which edge of the pair
    int sub  = lane & 15;       // 16B chunk within 256B row
    int beg = g_rowptr[d], end = g_rowptr[d + 1];
    float acc[8];
#pragma unroll
    for (int k = 0; k < 8; k++) acc[k] = 0.f;

    int j = beg;
    for (; j + 3 < end; j += 4) {
        int s0 = g_esrc[j + half];
        int s1 = g_esrc[j + 2 + half];
        uint4 va = *reinterpret_cast<const uint4*>(g_xh + (size_t)s0 * DIM + sub * 8);
        uint4 vb = *reinterpret_cast<const uint4*>(g_xh + (size_t)s1 * DIM + sub * 8);
        __half2 p0 = __hadd2(*reinterpret_cast<__half2*>(&va.x), *reinterpret_cast<__half2*>(&vb.x));
        __half2 p1 = __hadd2(*reinterpret_cast<__half2*>(&va.y), *reinterpret_cast<__half2*>(&vb.y));
        __half2 p2 = __hadd2(*reinterpret_cast<__half2*>(&va.z), *reinterpret_cast<__half2*>(&vb.z));
        __half2 p3 = __hadd2(*reinterpret_cast<__half2*>(&va.w), *reinterpret_cast<__half2*>(&vb.w));
        float2 f0 = __half22float2(p0); acc[0] += f0.x; acc[1] += f0.y;
        float2 f1 = __half22float2(p1); acc[2] += f1.x; acc[3] += f1.y;
        float2 f2 = __half22float2(p2); acc[4] += f2.x; acc[5] += f2.y;
        float2 f3 = __half22float2(p3); acc[6] += f3.x; acc[7] += f3.y;
    }
    for (; j < end; j += 2) {
        int jj = j + half;
        if (jj < end) {
            int s = g_esrc[jj];
            uint4 v = *reinterpret_cast<const uint4*>(g_xh + (size_t)s * DIM + sub * 8);
            float2 f0 = __half22float2(*reinterpret_cast<__half2*>(&v.x)); acc[0] += f0.x; acc[1] += f0.y;
            float2 f1 = __half22float2(*reinterpret_cast<__half2*>(&v.y)); acc[2] += f1.x; acc[3] += f1.y;
            float2 f2 = __half22float2(*reinterpret_cast<__half2*>(&v.z)); acc[4] += f2.x; acc[5] += f2.y;
            float2 f3 = __half22float2(*reinterpret_cast<__half2*>(&v.w)); acc[6] += f3.x; acc[7] += f3.y;
        }
    }
#pragma unroll
    for (int k = 0; k < 8; k++) acc[k] += __shfl_xor_sync(0xffffffffu, acc[k], 16);
    if (half == 0) {
        float inv = 1.f / fmaxf((float)(end - beg), 1.f);
        float4 o0 = make_float4(acc[0] * inv, acc[1] * inv, acc[2] * inv, acc[3] * inv);
        float4 o1 = make_float4(acc[4] * inv, acc[5] * inv, acc[6] * inv, acc[7] * inv);
        float4* outp = reinterpret_cast<float4*>(g_xa + (size_t)d * DIM + sub * 8);
        outp[0] = o0;
        outp[1] = o1;
    }
}

// ---------------- agg2: warp per listed dst, half-warps gather 2 edges (fp32 rows, 256B) --------
__global__ __launch_bounds__(256) void agg2_csr_kernel() {
    int idx = blockIdx.x * 8 + (threadIdx.x >> 5);
    if (idx >= g_nlist) return;
    int d = g_list[idx];
    int lane = threadIdx.x & 31;
    int half = lane >> 4;
    int sub  = lane & 15;       // 16B chunk within 256B row (4 floats)
    int beg = g_rowptr[d], end = g_rowptr[d + 1];
    float acc[4] = {0.f, 0.f, 0.f, 0.f};

    int j = beg;
    for (; j + 3 < end; j += 4) {
        int s0 = g_esrc[j + half];
        int s1 = g_esrc[j + 2 + half];
        float4 va = *reinterpret_cast<const float4*>(g_p + (size_t)s0 * DEMB + sub * 4);
        float4 vb = *reinterpret_cast<const float4*>(g_p + (size_t)s1 * DEMB + sub * 4);
        acc[0] += va.x + vb.x; acc[1] += va.y + vb.y;
        acc[2] += va.z + vb.z; acc[3] += va.w + vb.w;
    }
    for (; j < end; j += 2) {
        int jj = j + half;
        if (jj < end) {
            int s = g_esrc[jj];
            float4 v = *reinterpret_cast<const float4*>(g_p + (size_t)s * DEMB + sub * 4);
            acc[0] += v.x; acc[1] += v.y; acc[2] += v.z; acc[3] += v.w;
        }
    }
#pragma unroll
    for (int k = 0; k < 4; k++) acc[k] += __shfl_xor_sync(0xffffffffu, acc[k], 16);
    if (half == 0) {
        float inv = 1.f / fmaxf((float)(end - beg), 1.f);
        reinterpret_cast<float4*>(g_pa + (size_t)d * DEMB + sub * 4)[0] =
            make_float4(acc[0] * inv, acc[1] * inv, acc[2] * inv, acc[3] * inv);
    }
}

// ---------------- fused GEMM: p = relu(xa@W1 + b1) @ W2   (64 rows/block, 512 threads, FFMA2) ------
__global__ __launch_bounds__(512) void fused_gemm_kernel(
    const float* __restrict__ W1, const float* __restrict__ b1,
    const float* __restrict__ W2) {
    extern __shared__ float sm[];
    float* W1s = sm;                       // 128*128
    float* W2s = W1s + 128 * 128;          // 128*64
    float* Is  = W2s + 128 * 64;           // 64*128
    float* Hs  = Is  + 64 * 128;           // 64*128
    float* b1s = Hs  + 64 * 128;           // 128
    int tid = threadIdx.x;

    for (int i = tid; i < 128 * 128 / 4; i += 512)
        reinterpret_cast<float4*>(W1s)[i] = reinterpret_cast<const float4*>(W1)[i];
    for (int i = tid; i < 128 * 64 / 4; i += 512)
        reinterpret_cast<float4*>(W2s)[i] = reinterpret_cast<const float4*>(W2)[i];
    if (tid < 128) b1s[tid] = b1[tid];

    int row0 = blockIdx.x * 64;  // 1250 blocks * 64 = 80000 exact
    for (int i = tid; i < 64 * DIM / 4; i += 512)
        reinterpret_cast<float4*>(Is)[i] =
            reinterpret_cast<const float4*>(g_xa + (size_t)row0 * DIM)[i];
    __syncthreads();

    int tr = tid >> 5, tc = tid & 31;   // tr 0..15, tc 0..31

    // phase 1: H = relu(Is @ W1 + b1); thread -> 4 rows x 4 cols (2 f32x2 pairs)
    {
        ull acc[4][2];
#pragma unroll
        for (int i = 0; i < 4; i++) { acc[i][0] = 0ull; acc[i][1] = 0ull; }

        for (int d0 = 0; d0 < DIM; d0 += 4) {
            float ar[4][4];
#pragma unroll
            for (int i = 0; i < 4; i++) {
                float4 t = reinterpret_cast<const float4*>(Is + (tr * 4 + i) * DIM)[d0 >> 2];
                ar[i][0] = t.x; ar[i][1] = t.y; ar[i][2] = t.z; ar[i][3] = t.w;
            }
#pragma unroll
            for (int dd = 0; dd < 4; dd++) {
                ulonglong2 wv = *reinterpret_cast<const ulonglong2*>(W1s + (d0 + dd) * 128 + tc * 4);
#pragma unroll
                for (int i = 0; i < 4; i++) {
                    ull ap = bcast2(ar[i][dd]);
                    acc[i][0] = ffma2(ap, wv.x, acc[i][0]);
                    acc[i][1] = ffma2(ap, wv.y, acc[i][1]);
                }
            }
        }
        float4 bv = reinterpret_cast<const float4*>(b1s)[tc];
#pragma unroll
        for (int i = 0; i < 4; i++) {
            float2 lo = unpack2(acc[i][0]);
            float2 hi = unpack2(acc[i][1]);
            float4 o;
            o.x = fmaxf(lo.x + bv.x, 0.f);
            o.y = fmaxf(lo.y + bv.y, 0.f);
            o.z = fmaxf(hi.x + bv.z, 0.f);
            o.w = fmaxf(hi.y + bv.w, 0.f);
            reinterpret_cast<float4*>(Hs + (tr * 4 + i) * DIM)[tc] = o;
        }
    }
    __syncthreads();

    // phase 2: P = Hs @ W2; thread -> 4 rows x 2 cols (1 f32x2 pair)
    {
        ull acc[4];
#pragma unroll
        for (int i = 0; i < 4; i++) acc[i] = 0ull;

        for (int d0 = 0; d0 < DIM; d0 += 4) {
            float ar[4][4];
#pragma unroll
            for (int i = 0; i < 4; i++) {
                float4 t = reinterpret_cast<const float4*>(Hs + (tr * 4 + i) * DIM)[d0 >> 2];
                ar[i][0] = t.x; ar[i][1] = t.y; ar[i][2] = t.z; ar[i][3] = t.w;
            }
#pragma unroll
            for (int dd = 0; dd < 4; dd++) {
                ull wp = *reinterpret_cast<const ull*>(W2s + (d0 + dd) * 64 + tc * 2);
#pragma unroll
                for (int i = 0; i < 4; i++)
                    acc[i] = ffma2(bcast2(ar[i][dd]), wp, acc[i]);
            }
        }
#pragma unroll
        for (int i = 0; i < 4; i++) {
            int row = row0 + tr * 4 + i;
            float2 o = unpack2(acc[i]);
            reinterpret_cast<float2*>(g_p + (size_t)row * DEMB)[tc] = o;
        }
    }
}

// ---------------- half-MLP: OutT[k][r] = sum_d (pa[node_r][d] + b2[d]) * Whalf[d][k] (+bm1[k]) ------
__global__ __launch_bounds__(128) void half_mlp_kernel(
    const int* __restrict__ list, int nrows,
    const float* __restrict__ Whalf, const float* __restrict__ b2,
    const float* __restrict__ bm1, float* __restrict__ OutT, int ldo) {
    __shared__ __align__(8) float Wst[128 * 66];   // transposed [t][d], pad 66 (even) for ull loads
    __shared__ __align__(8) float es[DEMB];
    int tid = threadIdx.x;  // 128 (= t)

#pragma unroll 4
    for (int d = 0; d < DEMB; d++) Wst[tid * 66 + d] = Whalf[d * DIM + tid];
    float base = bm1 ? bm1[tid] : 0.f;

    for (int r = blockIdx.x; r < nrows; r += gridDim.x) {
        __syncthreads();
        if (tid < DEMB) {
            int node = NUMP + list[r];
            es[tid] = g_pa[(size_t)node * DEMB + tid] + b2[tid];
        }
        __syncthreads();
        ull acc = 0ull;
#pragma unroll 8
        for (int d = 0; d < DEMB; d += 2) {
            ull ep = *reinterpret_cast<const ull*>(es + d);
            ull wp = *reinterpret_cast<const ull*>(Wst + tid * 66 + d);
            acc = ffma2(ep, wp, acc);
        }
        float2 a2 = unpack2(acc);
        OutT[(size_t)tid * ldo + r] = base + a2.x + a2.y;
    }
}

// ---------------- pair kernel: out[t*NG+g] = softmax( relu(A[t]+B[g]) @ Wm2 + bm2 ) ----------------
__global__ __launch_bounds__(256) void pair_kernel(
    const float* __restrict__ Wm2, const float* __restrict__ bm2, float* __restrict__ out) {
    extern __shared__ float sm[];
    float* As = sm;                       // [k][t] 128*128
    float* Bs = sm + DIM * NT;            // [k][gl] 128*32
    float2* w2 = reinterpret_cast<float2*>(sm + DIM * NT + DIM * 32);
    int tid = threadIdx.x;  // 256

    for (int i = tid; i < DIM * NT / 4; i += 256)
        reinterpret_cast<float4*>(As)[i] = reinterpret_cast<const float4*>(g_At)[i];
    int g0 = blockIdx.x * 32;
    for (int i = tid; i < DIM * 32; i += 256) {
        int k = i >> 5, gl = i & 31;
        Bs[i] = g_Bt[(size_t)k * NG + g0 + gl];
    }
    if (tid < DIM) w2[tid] = reinterpret_cast<const float2*>(Wm2)[tid];
    __syncthreads();

    float bo0 = bm2[0], bo1 = bm2[1];
    int lane = tid & 31, warp = tid >> 5;
    ull accp[16];
#pragma unroll
    for (int i = 0; i < 16; i++) accp[i] = 0ull;

#pragma unroll 4
    for (int k = 0; k < DIM; k++) {
        float bv = Bs[k * 32 + lane];
        ull wp = *reinterpret_cast<const ull*>(&w2[k]);
#pragma unroll
        for (int i = 0; i < 16; i++) {
            float a = As[k * DIM + warp + 8 * i];
            float v = fmaxf(a + bv, 0.f);
            accp[i] = ffma2(bcast2(v), wp, accp[i]);
        }
    }

#pragma unroll
    for (int i = 0; i < 16; i++) {
        int t = warp + 8 * i;
        float2 a2 = unpack2(accp[i]);
        float o0 = a2.x + bo0, o1 = a2.y + bo1;
        float m  = fmaxf(o0, o1);
        float e0 = __expf(o0 - m), e1 = __expf(o1 - m);
        float inv = 1.f / (e0 + e1);
        reinterpret_cast<float2*>(out)[(size_t)t * NG + g0 + lane] = make_float2(e0 * inv, e1 * inv);
    }
}

// ---------------- launch ----------------
extern "C" void kernel_launch(void* const* d_in, const int* in_sizes, int n_in,
                              void* d_out, int out_size) {
    const float* x   = (const float*)d_in[0];
    const float* W1  = (const float*)d_in[1];
    const float* b1  = (const float*)d_in[2];
    const float* W2  = (const float*)d_in[3];
    const float* b2  = (const float*)d_in[4];
    const float* Wm1 = (const float*)d_in[5];
    const float* bm1 = (const float*)d_in[6];
    const float* Wm2 = (const float*)d_in[7];
    const float* bm2 = (const float*)d_in[8];
    const int* edges = (const int*)d_in[9];
    const int* tf    = (const int*)d_in[11];
    const int* gene  = (const int*)d_in[12];
    int ne = in_sizes[9] / 2;
    const int* src = edges;
    const int* dst = edges + ne;
    float* out = (float*)d_out;

    const int fused_smem = (128 * 128 + 128 * 64 + 64 * 128 + 64 * 128 + 128) * 4;
    cudaFuncSetAttribute(fused_gemm_kernel, cudaFuncAttributeMaxDynamicSharedMemorySize, fused_smem);
    cudaFuncSetAttribute(pair_kernel, cudaFuncAttributeMaxDynamicSharedMemorySize,
                         (DIM * NT + DIM * 32) * 4 + DIM * 8);

    void *p_At, *p_Bt;
    cudaGetSymbolAddress(&p_At, g_At);
    cudaGetSymbolAddress(&p_Bt, g_Bt);

    const int nb_scan = (NNODES + 1 + 1023) / 1024;  // 79
    int hb = (ne + 255) / 256;
    int combo_blocks = hb + 5000 + (NG + 255) / 256;

    zero_kernel<<<(NNODES + 1 + 255) / 256, 256>>>();
    combo_kernel<<<combo_blocks, 256>>>(x, dst, ne, hb, tf, gene);
    scan1_kernel<<<nb_scan, 1024>>>();
    scan2_kernel<<<1, 32>>>(nb_scan);
    scan3_kernel<<<nb_scan, 1024>>>();
    scatter_kernel<<<(ne + 255) / 256, 256>>>(src, dst, ne);
    agg1_csr_kernel<<<NNODES / 8, 256>>>();
    fused_gemm_kernel<<<NNODES / 64, 512, fused_smem>>>(W1, b1, W2);
    agg2_csr_kernel<<<(NT + NG + 7) / 8, 256>>>();
    half_mlp_kernel<<<NT, 128>>>(tf, NT, Wm1, b2, nullptr, (float*)p_At, NT);
    half_mlp_kernel<<<1000, 128>>>(gene, NG, Wm1 + 64 * DIM, b2, bm1, (float*)p_Bt, NG);
    pair_kernel<<<NG / 32, 256, (DIM * NT + DIM * 32) * 4 + DIM * 8>>>(Wm2, bm2, out);
}